// round 1
// baseline (speedup 1.0000x reference)
#include <cuda_runtime.h>
#include <cuda_bf16.h>

#define N_USER 50000
#define N_ITEM 100000
#define NTOT   150000
#define DEMB   64
#define NNZT   2400000
#define BSZ    4096
#define NLAYER 3
#define NEG_SLOPE 0.2f

// ------------------- static device scratch (no allocations allowed) -------------------
__device__ __align__(256) float g_E0[NTOT * DEMB];            // concat(user_emb, item_emb)
__device__ __align__(256) float g_Elay[NLAYER][NTOT * DEMB];  // unnormalized layer outputs
__device__ __align__(256) float g_inorm[NLAYER][NTOT];        // 1/max(norm,eps) per layer
__device__ int   g_cnt[NTOT + 1];
__device__ int   g_off[NTOT + 1];
__device__ int   g_cur[NTOT + 1];
__device__ int   g_colv[NNZT];
__device__ float g_valv[NNZT];
__device__ int   g_part[256];

// ------------------- CSR build -------------------
__global__ void k_zero_cnt() {
    int i = blockIdx.x * blockDim.x + threadIdx.x;
    if (i <= NTOT) g_cnt[i] = 0;
}

__global__ void k_concat(const float4* __restrict__ ue, const float4* __restrict__ ie) {
    int i = blockIdx.x * blockDim.x + threadIdx.x;  // over NTOT*16 float4
    if (i < N_USER * (DEMB / 4)) {
        ((float4*)g_E0)[i] = ue[i];
    } else if (i < NTOT * (DEMB / 4)) {
        ((float4*)g_E0)[i] = ie[i - N_USER * (DEMB / 4)];
    }
}

__global__ void k_count(const int* __restrict__ rows) {
    int e = blockIdx.x * blockDim.x + threadIdx.x;
    if (e < NNZT) atomicAdd(&g_cnt[rows[e]], 1);
}

#define SCAN_NBLK 147

__global__ void k_scan1() {
    __shared__ int s[1024];
    int t = threadIdx.x;
    int i = blockIdx.x * 1024 + t;
    int x = (i <= NTOT) ? g_cnt[i] : 0;
    s[t] = x;
    __syncthreads();
    for (int d = 512; d > 0; d >>= 1) {
        if (t < d) s[t] += s[t + d];
        __syncthreads();
    }
    if (t == 0) g_part[blockIdx.x] = s[0];
}

__global__ void k_scan2() {
    if (threadIdx.x == 0 && blockIdx.x == 0) {
        int run = 0;
        for (int b = 0; b < SCAN_NBLK; b++) {
            int v = g_part[b];
            g_part[b] = run;
            run += v;
        }
    }
}

__global__ void k_scan3() {
    __shared__ int s[1024];
    int t = threadIdx.x;
    int i = blockIdx.x * 1024 + t;
    int x = (i <= NTOT) ? g_cnt[i] : 0;
    s[t] = x;
    __syncthreads();
    // Hillis-Steele inclusive scan
    for (int d = 1; d < 1024; d <<= 1) {
        int v = (t >= d) ? s[t - d] : 0;
        __syncthreads();
        s[t] += v;
        __syncthreads();
    }
    int excl = g_part[blockIdx.x] + s[t] - x;
    if (i <= NTOT) {
        g_off[i] = excl;
        g_cur[i] = excl;
    }
}

__global__ void k_fill(const int* __restrict__ rows, const int* __restrict__ cols,
                       const float* __restrict__ vals) {
    int e = blockIdx.x * blockDim.x + threadIdx.x;
    if (e < NNZT) {
        int r = rows[e];
        int p = atomicAdd(&g_cur[r], 1);
        g_colv[p] = cols[e];
        g_valv[p] = vals[e];
    }
}

// ------------------- fused layer: SpMM gather + (a@W1 + m@W2 + b) + leaky + norm -------------------
#define LW 16  // rows (warps) per block; blockDim = 512

__global__ __launch_bounds__(512) void k_layer(int layer,
                                               const float* __restrict__ W1l,
                                               const float* __restrict__ W2l,
                                               const float* __restrict__ b1l,
                                               const float* __restrict__ b2l) {
    __shared__ __align__(16) float sW1[DEMB * DEMB];
    __shared__ __align__(16) float sW2[DEMB * DEMB];
    __shared__ __align__(16) float sB[DEMB];
    __shared__ __align__(16) float sAM[LW][2 * DEMB];

    const float* __restrict__ Eprev = (layer == 0) ? g_E0 : g_Elay[layer - 1];
    float* __restrict__ Eout = g_Elay[layer];
    float* __restrict__ inorm = g_inorm[layer];

    int tid = threadIdx.x;
    // stage weights (1024 float4 per matrix)
    const float4* w1v = (const float4*)W1l;
    const float4* w2v = (const float4*)W2l;
    for (int i = tid; i < DEMB * DEMB / 4; i += 512) {
        ((float4*)sW1)[i] = w1v[i];
        ((float4*)sW2)[i] = w2v[i];
    }
    if (tid < DEMB) sB[tid] = b1l[tid] + b2l[tid];
    __syncthreads();

    int warp = tid >> 5, lane = tid & 31;
    int ngroups = (NTOT + LW - 1) / LW;

    for (int g = blockIdx.x; g < ngroups; g += gridDim.x) {
        int r = g * LW + warp;
        if (r < NTOT) {
            int s = g_off[r], e2 = g_off[r + 1];
            float2 acc = make_float2(0.f, 0.f);
            for (int base = s; base < e2; base += 32) {
                int c = 0;
                float v = 0.f;
                if (base + lane < e2) {
                    c = g_colv[base + lane];
                    v = g_valv[base + lane];
                }
                int cnt = min(32, e2 - base);
                for (int i = 0; i < cnt; i++) {
                    int cc = __shfl_sync(0xffffffffu, c, i);
                    float vv = __shfl_sync(0xffffffffu, v, i);
                    float2 x = *(const float2*)&Eprev[cc * DEMB + lane * 2];
                    acc.x = fmaf(vv, x.x, acc.x);
                    acc.y = fmaf(vv, x.y, acc.y);
                }
            }
            float2 e0 = *(const float2*)&Eprev[r * DEMB + lane * 2];
            float2 a = make_float2(acc.x + e0.x, acc.y + e0.y);
            float2 m = make_float2(acc.x * e0.x, acc.y * e0.y);
            *(float2*)&sAM[warp][lane * 2] = a;
            *(float2*)&sAM[warp][DEMB + lane * 2] = m;
        }
        __syncwarp();
        if (r < NTOT) {
            int j = lane * 2;
            float acc0 = sB[j], acc1 = sB[j + 1];
            const float* am = sAM[warp];
#pragma unroll 16
            for (int k = 0; k < DEMB; k++) {
                float ak = am[k];
                float mk = am[DEMB + k];
                float2 w1 = *(const float2*)&sW1[k * DEMB + j];
                float2 w2 = *(const float2*)&sW2[k * DEMB + j];
                acc0 = fmaf(ak, w1.x, acc0);
                acc0 = fmaf(mk, w2.x, acc0);
                acc1 = fmaf(ak, w1.y, acc1);
                acc1 = fmaf(mk, w2.y, acc1);
            }
            float h0 = acc0 > 0.f ? acc0 : NEG_SLOPE * acc0;
            float h1 = acc1 > 0.f ? acc1 : NEG_SLOPE * acc1;
            float ss = h0 * h0 + h1 * h1;
#pragma unroll
            for (int d = 16; d > 0; d >>= 1) ss += __shfl_xor_sync(0xffffffffu, ss, d);
            *(float2*)&Eout[r * DEMB + j] = make_float2(h0, h1);
            if (lane == 0) inorm[r] = 1.0f / fmaxf(sqrtf(ss), 1e-12f);
        }
        __syncwarp();
    }
}

// ------------------- final gather -------------------
__global__ void k_gather(const int* __restrict__ users, const int* __restrict__ pos,
                         const int* __restrict__ neg, float* __restrict__ out) {
    int b = blockIdx.x;         // [0, 3*BSZ)
    int grp = b >> 12;          // /4096
    int i = b & (BSZ - 1);
    int node;
    if (grp == 0) node = users[i] - 1;
    else if (grp == 1) node = N_USER + pos[i] - 1;
    else node = N_USER + neg[i] - 1;

    int j = threadIdx.x;        // 0..255
    int l = j >> 6, jj = j & 63;
    float v;
    if (l == 0) {
        v = g_E0[node * DEMB + jj];
    } else {
        v = g_Elay[l - 1][node * DEMB + jj] * g_inorm[l - 1][node];
    }
    out[(size_t)b * 256 + j] = v;
}

// ------------------- launch -------------------
extern "C" void kernel_launch(void* const* d_in, const int* in_sizes, int n_in,
                              void* d_out, int out_size) {
    const float* ue = (const float*)d_in[0];
    const float* ie = (const float*)d_in[1];
    const float* ev = (const float*)d_in[2];
    const float* W1 = (const float*)d_in[3];
    const float* b1 = (const float*)d_in[4];
    const float* W2 = (const float*)d_in[5];
    const float* b2 = (const float*)d_in[6];
    const int* eidx = (const int*)d_in[7];
    const int* users = (const int*)d_in[8];
    const int* pos = (const int*)d_in[9];
    const int* neg = (const int*)d_in[10];
    float* out = (float*)d_out;

    const int* rows = eidx;
    const int* cols = eidx + NNZT;

    k_zero_cnt<<<(NTOT + 1 + 255) / 256, 256>>>();
    k_concat<<<(NTOT * (DEMB / 4) + 255) / 256, 256>>>((const float4*)ue, (const float4*)ie);
    k_count<<<(NNZT + 255) / 256, 256>>>(rows);
    k_scan1<<<SCAN_NBLK, 1024>>>();
    k_scan2<<<1, 32>>>();
    k_scan3<<<SCAN_NBLK, 1024>>>();
    k_fill<<<(NNZT + 255) / 256, 256>>>(rows, cols, ev);

    for (int l = 0; l < NLAYER; l++) {
        k_layer<<<592, 512>>>(l, W1 + l * DEMB * DEMB, W2 + l * DEMB * DEMB,
                              b1 + l * DEMB, b2 + l * DEMB);
    }
    k_gather<<<3 * BSZ, 256>>>(users, pos, neg, out);
}

// round 4
// speedup vs baseline: 1.7056x; 1.7056x over previous
#include <cuda_runtime.h>
#include <cuda_bf16.h>

#define N_USER 50000
#define N_ITEM 100000
#define NTOT   150000
#define DEMB   64
#define NNZT   2400000
#define BSZ    4096
#define NLAYER 3
#define NEG_SLOPE 0.2f

// ------------------- static device scratch -------------------
__device__ __align__(256) float g_E0[NTOT * DEMB];            // concat(user_emb, item_emb)
__device__ __align__(256) float g_Elay[NLAYER][NTOT * DEMB];  // unnormalized layer outputs
__device__ __align__(256) float g_inorm[NLAYER][NTOT];        // 1/max(norm,eps)
__device__ __align__(256) float g_AM[NTOT * 2 * DEMB];        // [a | m] GEMM operand
__device__ int  g_cnt[NTOT + 1];
__device__ int  g_off[NTOT + 1];
__device__ int  g_cur[NTOT + 1];
__device__ int2 g_cv[NNZT];                                   // packed (col, val-bits)
__device__ int  g_part[256];

// ------------------- CSR build -------------------
__global__ void k_zero_cnt() {
    int i = blockIdx.x * blockDim.x + threadIdx.x;
    if (i <= NTOT) g_cnt[i] = 0;
}

__global__ void k_concat(const float4* __restrict__ ue, const float4* __restrict__ ie) {
    int i = blockIdx.x * blockDim.x + threadIdx.x;
    if (i < N_USER * (DEMB / 4)) {
        ((float4*)g_E0)[i] = ue[i];
    } else if (i < NTOT * (DEMB / 4)) {
        ((float4*)g_E0)[i] = ie[i - N_USER * (DEMB / 4)];
    }
}

__global__ void k_count(const int* __restrict__ rows) {
    int e = blockIdx.x * blockDim.x + threadIdx.x;
    if (e < NNZT) atomicAdd(&g_cnt[rows[e]], 1);
}

#define SCAN_NBLK 147

__global__ void k_scan1() {
    __shared__ int s[1024];
    int t = threadIdx.x;
    int i = blockIdx.x * 1024 + t;
    int x = (i <= NTOT) ? g_cnt[i] : 0;
    s[t] = x;
    __syncthreads();
    for (int d = 512; d > 0; d >>= 1) {
        if (t < d) s[t] += s[t + d];
        __syncthreads();
    }
    if (t == 0) g_part[blockIdx.x] = s[0];
}

__global__ void k_scan2() {
    if (threadIdx.x == 0 && blockIdx.x == 0) {
        int run = 0;
        for (int b = 0; b < SCAN_NBLK; b++) {
            int v = g_part[b];
            g_part[b] = run;
            run += v;
        }
    }
}

__global__ void k_scan3() {
    __shared__ int s[1024];
    int t = threadIdx.x;
    int i = blockIdx.x * 1024 + t;
    int x = (i <= NTOT) ? g_cnt[i] : 0;
    s[t] = x;
    __syncthreads();
    for (int d = 1; d < 1024; d <<= 1) {
        int v = (t >= d) ? s[t - d] : 0;
        __syncthreads();
        s[t] += v;
        __syncthreads();
    }
    int excl = g_part[blockIdx.x] + s[t] - x;
    if (i <= NTOT) {
        g_off[i] = excl;
        g_cur[i] = excl;
    }
}

__global__ void k_fill(const int* __restrict__ rows, const int* __restrict__ cols,
                       const float* __restrict__ vals) {
    int e = blockIdx.x * blockDim.x + threadIdx.x;
    if (e < NNZT) {
        int r = rows[e];
        int p = atomicAdd(&g_cur[r], 1);
        g_cv[p] = make_int2(cols[e], __float_as_int(vals[e]));
    }
}

// ------------------- SpMM gather: writes AM = [LE+E | LE*E] -------------------
#define SW 16  // warps per block

__global__ __launch_bounds__(512) void k_spmm(int layer) {
    const float* __restrict__ Eprev = (layer == 0) ? g_E0 : g_Elay[layer - 1];
    int tid = threadIdx.x;
    int warp = tid >> 5, lane = tid & 31;
    int ngroups = (NTOT + SW - 1) / SW;

    for (int g = blockIdx.x; g < ngroups; g += gridDim.x) {
        int r = g * SW + warp;
        if (r >= NTOT) continue;
        int s = g_off[r], e2 = g_off[r + 1];
        float2 acc = make_float2(0.f, 0.f);
        for (int base = s; base < e2; base += 32) {
            int2 cv = make_int2(0, 0);
            if (base + lane < e2) cv = g_cv[base + lane];
            int cnt = min(32, e2 - base);
            int cnt8 = (cnt + 7) & ~7;
            for (int i = 0; i < cnt8; i += 8) {
#pragma unroll
                for (int u = 0; u < 8; u++) {
                    int cc = __shfl_sync(0xffffffffu, cv.x, i + u);
                    float vv = __int_as_float(__shfl_sync(0xffffffffu, cv.y, i + u));
                    float2 x = *(const float2*)&Eprev[cc * DEMB + lane * 2];
                    acc.x = fmaf(vv, x.x, acc.x);
                    acc.y = fmaf(vv, x.y, acc.y);
                }
            }
        }
        float2 e0 = *(const float2*)&Eprev[r * DEMB + lane * 2];
        *(float2*)&g_AM[r * 128 + lane * 2] =
            make_float2(acc.x + e0.x, acc.y + e0.y);
        *(float2*)&g_AM[r * 128 + DEMB + lane * 2] =
            make_float2(acc.x * e0.x, acc.y * e0.y);
    }
}

// ------------------- tiled GEMM: Eout = leaky(AM @ [W1;W2] + b), + row inv-norm -------------------
#define BM 128
#define BN 64
#define BK 16
#define PADA 4
#define PADB 4

__global__ __launch_bounds__(128) void k_gemm(int layer,
                                              const float* __restrict__ W1l,
                                              const float* __restrict__ W2l,
                                              const float* __restrict__ b1l,
                                              const float* __restrict__ b2l) {
    __shared__ __align__(16) float sA[BK][BM + PADA];
    __shared__ __align__(16) float sB[BK][BN + PADB];
    __shared__ float sBias[BN];

    float* __restrict__ Eout = g_Elay[layer];
    float* __restrict__ inorm = g_inorm[layer];

    int tid = threadIdx.x;
    int tx = tid & 7;    // 8 col-groups of 8
    int ty = tid >> 3;   // 16 row-groups of 8
    int m0 = blockIdx.x * BM;

    if (tid < BN) sBias[tid] = b1l[tid] + b2l[tid];

    float acc[8][8];
#pragma unroll
    for (int i = 0; i < 8; i++)
#pragma unroll
        for (int j = 0; j < 8; j++) acc[i][j] = 0.f;

    for (int k0 = 0; k0 < 2 * DEMB; k0 += BK) {
        // A tile: rows m0..m0+127, cols k0..k0+15 -> sA[k][m] (transposed)
#pragma unroll
        for (int i = 0; i < 4; i++) {
            int idx = tid + i * 128;        // float4 index 0..511
            int m = idx >> 2;
            int kq = (idx & 3) * 4;
            float4 v = make_float4(0.f, 0.f, 0.f, 0.f);
            int gr = m0 + m;
            if (gr < NTOT) v = *(const float4*)&g_AM[gr * 128 + k0 + kq];
            sA[kq + 0][m] = v.x;
            sA[kq + 1][m] = v.y;
            sA[kq + 2][m] = v.z;
            sA[kq + 3][m] = v.w;
        }
        // B tile: Wcat rows k0..k0+15 (W1 rows then W2 rows), cols 0..63
#pragma unroll
        for (int i = 0; i < 2; i++) {
            int idx = tid + i * 128;        // float4 index 0..255
            int kr = idx >> 4;
            int cq = (idx & 15) * 4;
            int gk = k0 + kr;
            const float* Wsrc = (gk < DEMB) ? (W1l + gk * DEMB) : (W2l + (gk - DEMB) * DEMB);
            *(float4*)&sB[kr][cq] = *(const float4*)&Wsrc[cq];
        }
        __syncthreads();
#pragma unroll
        for (int kk = 0; kk < BK; kk++) {
            float a[8], b[8];
            *(float4*)&a[0] = *(float4*)&sA[kk][ty * 8];
            *(float4*)&a[4] = *(float4*)&sA[kk][ty * 8 + 4];
            *(float4*)&b[0] = *(float4*)&sB[kk][tx * 8];
            *(float4*)&b[4] = *(float4*)&sB[kk][tx * 8 + 4];
#pragma unroll
            for (int i = 0; i < 8; i++)
#pragma unroll
                for (int j = 0; j < 8; j++)
                    acc[i][j] = fmaf(a[i], b[j], acc[i][j]);
        }
        __syncthreads();
    }

    float bias[8];
    *(float4*)&bias[0] = *(float4*)&sBias[tx * 8];
    *(float4*)&bias[4] = *(float4*)&sBias[tx * 8 + 4];

#pragma unroll
    for (int i = 0; i < 8; i++) {
        int r = m0 + ty * 8 + i;
        float h[8];
        float ss = 0.f;
#pragma unroll
        for (int j = 0; j < 8; j++) {
            float v = acc[i][j] + bias[j];
            v = v > 0.f ? v : NEG_SLOPE * v;
            h[j] = v;
            ss = fmaf(v, v, ss);
        }
        ss += __shfl_xor_sync(0xffffffffu, ss, 1);
        ss += __shfl_xor_sync(0xffffffffu, ss, 2);
        ss += __shfl_xor_sync(0xffffffffu, ss, 4);
        if (r < NTOT) {
            *(float4*)&Eout[r * DEMB + tx * 8] = *(float4*)&h[0];
            *(float4*)&Eout[r * DEMB + tx * 8 + 4] = *(float4*)&h[4];
            if (tx == 0) inorm[r] = 1.0f / fmaxf(sqrtf(ss), 1e-12f);
        }
    }
}

// ------------------- final gather -------------------
__global__ void k_gather(const int* __restrict__ users, const int* __restrict__ pos,
                         const int* __restrict__ neg, float* __restrict__ out) {
    int b = blockIdx.x;
    int grp = b >> 12;
    int i = b & (BSZ - 1);
    int node;
    if (grp == 0) node = users[i] - 1;
    else if (grp == 1) node = N_USER + pos[i] - 1;
    else node = N_USER + neg[i] - 1;

    int j = threadIdx.x;  // 0..255
    int l = j >> 6, jj = j & 63;
    float v;
    if (l == 0) {
        v = g_E0[node * DEMB + jj];
    } else {
        v = g_Elay[l - 1][node * DEMB + jj] * g_inorm[l - 1][node];
    }
    out[(size_t)b * 256 + j] = v;
}

// ------------------- launch -------------------
extern "C" void kernel_launch(void* const* d_in, const int* in_sizes, int n_in,
                              void* d_out, int out_size) {
    const float* ue = (const float*)d_in[0];
    const float* ie = (const float*)d_in[1];
    const float* ev = (const float*)d_in[2];
    const float* W1 = (const float*)d_in[3];
    const float* b1 = (const float*)d_in[4];
    const float* W2 = (const float*)d_in[5];
    const float* b2 = (const float*)d_in[6];
    const int* eidx = (const int*)d_in[7];
    const int* users = (const int*)d_in[8];
    const int* pos = (const int*)d_in[9];
    const int* neg = (const int*)d_in[10];
    float* out = (float*)d_out;

    const int* rows = eidx;
    const int* cols = eidx + NNZT;

    k_zero_cnt<<<(NTOT + 1 + 255) / 256, 256>>>();
    k_concat<<<(NTOT * (DEMB / 4) + 255) / 256, 256>>>((const float4*)ue, (const float4*)ie);
    k_count<<<(NNZT + 255) / 256, 256>>>(rows);
    k_scan1<<<SCAN_NBLK, 1024>>>();
    k_scan2<<<1, 32>>>();
    k_scan3<<<SCAN_NBLK, 1024>>>();
    k_fill<<<(NNZT + 255) / 256, 256>>>(rows, cols, ev);

    for (int l = 0; l < NLAYER; l++) {
        k_spmm<<<592, 512>>>(l);
        k_gemm<<<(NTOT + BM - 1) / BM, 128>>>(l, W1 + l * DEMB * DEMB, W2 + l * DEMB * DEMB,
                                              b1 + l * DEMB, b2 + l * DEMB);
    }
    k_gather<<<3 * BSZ, 256>>>(users, pos, neg, out);
}

// round 5
// speedup vs baseline: 1.7285x; 1.0134x over previous
#include <cuda_runtime.h>
#include <cuda_bf16.h>

#define N_USER 50000
#define N_ITEM 100000
#define NTOT   150000
#define DEMB   64
#define NNZT   2400000
#define BSZ    4096
#define NLAYER 3
#define NEG_SLOPE 0.2f

// ------------------- static device scratch -------------------
__device__ __align__(256) float g_E0[NTOT * DEMB];            // concat(user_emb, item_emb)
__device__ __align__(256) float g_Elay[NLAYER][NTOT * DEMB];  // unnormalized layer outputs
__device__ __align__(256) float g_inorm[NLAYER][NTOT];        // 1/max(norm,eps)
__device__ __align__(256) float g_AM[NTOT * 2 * DEMB];        // [a | m] GEMM operand
__device__ int  g_cnt[NTOT + 1];
__device__ int  g_off[NTOT + 1];
__device__ int  g_cur[NTOT + 1];
__device__ int2 g_cv[NNZT];                                   // packed (col, val-bits)
__device__ int  g_part[256];

// packed f32x2 helpers (Blackwell FFMA2 — PTX-only, ptxas never auto-fuses)
__device__ __forceinline__ unsigned long long pack2(float x, float y) {
    unsigned long long r;
    asm("mov.b64 %0, {%1, %2};" : "=l"(r) : "f"(x), "f"(y));
    return r;
}
__device__ __forceinline__ void unpack2(unsigned long long v, float& x, float& y) {
    asm("mov.b64 {%0, %1}, %2;" : "=f"(x), "=f"(y) : "l"(v));
}
__device__ __forceinline__ void fma2(unsigned long long& d, unsigned long long a,
                                     unsigned long long b) {
    asm("fma.rn.f32x2 %0, %1, %2, %0;" : "+l"(d) : "l"(a), "l"(b));
}

// ------------------- CSR build -------------------
__global__ void k_zero_cnt() {
    int i = blockIdx.x * blockDim.x + threadIdx.x;
    if (i <= NTOT) g_cnt[i] = 0;
}

__global__ void k_concat(const float4* __restrict__ ue, const float4* __restrict__ ie) {
    int i = blockIdx.x * blockDim.x + threadIdx.x;
    if (i < N_USER * (DEMB / 4)) {
        ((float4*)g_E0)[i] = ue[i];
    } else if (i < NTOT * (DEMB / 4)) {
        ((float4*)g_E0)[i] = ie[i - N_USER * (DEMB / 4)];
    }
}

__global__ void k_count(const int* __restrict__ rows) {
    int e = blockIdx.x * blockDim.x + threadIdx.x;
    if (e < NNZT) atomicAdd(&g_cnt[rows[e]], 1);
}

#define SCAN_NBLK 147

__global__ void k_scan1() {
    __shared__ int s[1024];
    int t = threadIdx.x;
    int i = blockIdx.x * 1024 + t;
    int x = (i <= NTOT) ? g_cnt[i] : 0;
    s[t] = x;
    __syncthreads();
    for (int d = 512; d > 0; d >>= 1) {
        if (t < d) s[t] += s[t + d];
        __syncthreads();
    }
    if (t == 0) g_part[blockIdx.x] = s[0];
}

__global__ void k_scan2() {
    if (threadIdx.x == 0 && blockIdx.x == 0) {
        int run = 0;
        for (int b = 0; b < SCAN_NBLK; b++) {
            int v = g_part[b];
            g_part[b] = run;
            run += v;
        }
    }
}

__global__ void k_scan3() {
    __shared__ int s[1024];
    int t = threadIdx.x;
    int i = blockIdx.x * 1024 + t;
    int x = (i <= NTOT) ? g_cnt[i] : 0;
    s[t] = x;
    __syncthreads();
    for (int d = 1; d < 1024; d <<= 1) {
        int v = (t >= d) ? s[t - d] : 0;
        __syncthreads();
        s[t] += v;
        __syncthreads();
    }
    int excl = g_part[blockIdx.x] + s[t] - x;
    if (i <= NTOT) {
        g_off[i] = excl;
        g_cur[i] = excl;
    }
}

__global__ void k_fill(const int* __restrict__ rows, const int* __restrict__ cols,
                       const float* __restrict__ vals) {
    int e = blockIdx.x * blockDim.x + threadIdx.x;
    if (e < NNZT) {
        int r = rows[e];
        int p = atomicAdd(&g_cur[r], 1);
        g_cv[p] = make_int2(cols[e], __float_as_int(vals[e]));
    }
}

// ------------------- SpMM gather: writes AM = [LE+E | LE*E] -------------------
#define SW 16  // warps per block

__global__ __launch_bounds__(512) void k_spmm(int layer) {
    const float* __restrict__ Eprev = (layer == 0) ? g_E0 : g_Elay[layer - 1];
    int tid = threadIdx.x;
    int warp = tid >> 5, lane = tid & 31;
    int ngroups = (NTOT + SW - 1) / SW;

    for (int g = blockIdx.x; g < ngroups; g += gridDim.x) {
        int r = g * SW + warp;
        if (r >= NTOT) continue;
        int s = g_off[r], e2 = g_off[r + 1];
        float2 acc = make_float2(0.f, 0.f);
        for (int base = s; base < e2; base += 32) {
            int2 cv = make_int2(0, 0);
            if (base + lane < e2) cv = g_cv[base + lane];
            int cnt = min(32, e2 - base);
            int cnt8 = (cnt + 7) & ~7;
            for (int i = 0; i < cnt8; i += 8) {
#pragma unroll
                for (int u = 0; u < 8; u++) {
                    int cc = __shfl_sync(0xffffffffu, cv.x, i + u);
                    float vv = __int_as_float(__shfl_sync(0xffffffffu, cv.y, i + u));
                    float2 x = *(const float2*)&Eprev[cc * DEMB + lane * 2];
                    acc.x = fmaf(vv, x.x, acc.x);
                    acc.y = fmaf(vv, x.y, acc.y);
                }
            }
        }
        float2 e0 = *(const float2*)&Eprev[r * DEMB + lane * 2];
        *(float2*)&g_AM[r * 128 + lane * 2] =
            make_float2(acc.x + e0.x, acc.y + e0.y);
        *(float2*)&g_AM[r * 128 + DEMB + lane * 2] =
            make_float2(acc.x * e0.x, acc.y * e0.y);
    }
}

// ------------------- tiled GEMM (FFMA2): Eout = leaky(AM @ [W1;W2] + b) + inv-norm -------------------
#define BM 128
#define BN 64
#define BK 16
#define PADA 4
#define PADB 4

__global__ __launch_bounds__(128) void k_gemm(int layer,
                                              const float* __restrict__ W1l,
                                              const float* __restrict__ W2l,
                                              const float* __restrict__ b1l,
                                              const float* __restrict__ b2l) {
    __shared__ __align__(16) float sA[BK][BM + PADA];
    __shared__ __align__(16) float sB[BK][BN + PADB];
    __shared__ float sBias[BN];

    float* __restrict__ Eout = g_Elay[layer];
    float* __restrict__ inorm = g_inorm[layer];

    int tid = threadIdx.x;
    int tx = tid & 7;    // 8 col-groups of 8
    int ty = tid >> 3;   // 16 row-groups of 8
    int m0 = blockIdx.x * BM;

    if (tid < BN) sBias[tid] = b1l[tid] + b2l[tid];

    unsigned long long acc2[8][4];  // [i][j-pair], each holds 2 fp32 accumulators
#pragma unroll
    for (int i = 0; i < 8; i++)
#pragma unroll
        for (int j = 0; j < 4; j++) acc2[i][j] = 0ull;

    for (int k0 = 0; k0 < 2 * DEMB; k0 += BK) {
        // A tile: rows m0..m0+127, cols k0..k0+15 -> sA[k][m] (transposed)
#pragma unroll
        for (int i = 0; i < 4; i++) {
            int idx = tid + i * 128;        // float4 index 0..511
            int m = idx >> 2;
            int kq = (idx & 3) * 4;
            float4 v = make_float4(0.f, 0.f, 0.f, 0.f);
            int gr = m0 + m;
            if (gr < NTOT) v = *(const float4*)&g_AM[gr * 128 + k0 + kq];
            sA[kq + 0][m] = v.x;
            sA[kq + 1][m] = v.y;
            sA[kq + 2][m] = v.z;
            sA[kq + 3][m] = v.w;
        }
        // B tile: Wcat rows k0..k0+15 (W1 rows then W2 rows), cols 0..63
#pragma unroll
        for (int i = 0; i < 2; i++) {
            int idx = tid + i * 128;        // float4 index 0..255
            int kr = idx >> 4;
            int cq = (idx & 15) * 4;
            int gk = k0 + kr;
            const float* Wsrc = (gk < DEMB) ? (W1l + gk * DEMB) : (W2l + (gk - DEMB) * DEMB);
            *(float4*)&sB[kr][cq] = *(const float4*)&Wsrc[cq];
        }
        __syncthreads();
#pragma unroll
        for (int kk = 0; kk < BK; kk++) {
            float a[8], b[8];
            *(float4*)&a[0] = *(float4*)&sA[kk][ty * 8];
            *(float4*)&a[4] = *(float4*)&sA[kk][ty * 8 + 4];
            *(float4*)&b[0] = *(float4*)&sB[kk][tx * 8];
            *(float4*)&b[4] = *(float4*)&sB[kk][tx * 8 + 4];
            unsigned long long ap[8], bp[4];
#pragma unroll
            for (int i = 0; i < 8; i++) ap[i] = pack2(a[i], a[i]);
#pragma unroll
            for (int j = 0; j < 4; j++) bp[j] = pack2(b[2 * j], b[2 * j + 1]);
#pragma unroll
            for (int i = 0; i < 8; i++)
#pragma unroll
                for (int j = 0; j < 4; j++)
                    fma2(acc2[i][j], ap[i], bp[j]);
        }
        __syncthreads();
    }

    float bias[8];
    *(float4*)&bias[0] = *(float4*)&sBias[tx * 8];
    *(float4*)&bias[4] = *(float4*)&sBias[tx * 8 + 4];

#pragma unroll
    for (int i = 0; i < 8; i++) {
        int r = m0 + ty * 8 + i;
        float h[8];
        float ss = 0.f;
#pragma unroll
        for (int j = 0; j < 4; j++) {
            float v0, v1;
            unpack2(acc2[i][j], v0, v1);
            v0 += bias[2 * j];
            v1 += bias[2 * j + 1];
            v0 = v0 > 0.f ? v0 : NEG_SLOPE * v0;
            v1 = v1 > 0.f ? v1 : NEG_SLOPE * v1;
            h[2 * j] = v0;
            h[2 * j + 1] = v1;
            ss = fmaf(v0, v0, ss);
            ss = fmaf(v1, v1, ss);
        }
        ss += __shfl_xor_sync(0xffffffffu, ss, 1);
        ss += __shfl_xor_sync(0xffffffffu, ss, 2);
        ss += __shfl_xor_sync(0xffffffffu, ss, 4);
        if (r < NTOT) {
            *(float4*)&Eout[r * DEMB + tx * 8] = *(float4*)&h[0];
            *(float4*)&Eout[r * DEMB + tx * 8 + 4] = *(float4*)&h[4];
            if (tx == 0) inorm[r] = 1.0f / fmaxf(sqrtf(ss), 1e-12f);
        }
    }
}

// ------------------- final gather -------------------
__global__ void k_gather(const int* __restrict__ users, const int* __restrict__ pos,
                         const int* __restrict__ neg, float* __restrict__ out) {
    int b = blockIdx.x;
    int grp = b >> 12;
    int i = b & (BSZ - 1);
    int node;
    if (grp == 0) node = users[i] - 1;
    else if (grp == 1) node = N_USER + pos[i] - 1;
    else node = N_USER + neg[i] - 1;

    int j = threadIdx.x;  // 0..255
    int l = j >> 6, jj = j & 63;
    float v;
    if (l == 0) {
        v = g_E0[node * DEMB + jj];
    } else {
        v = g_Elay[l - 1][node * DEMB + jj] * g_inorm[l - 1][node];
    }
    out[(size_t)b * 256 + j] = v;
}

// ------------------- launch -------------------
extern "C" void kernel_launch(void* const* d_in, const int* in_sizes, int n_in,
                              void* d_out, int out_size) {
    const float* ue = (const float*)d_in[0];
    const float* ie = (const float*)d_in[1];
    const float* ev = (const float*)d_in[2];
    const float* W1 = (const float*)d_in[3];
    const float* b1 = (const float*)d_in[4];
    const float* W2 = (const float*)d_in[5];
    const float* b2 = (const float*)d_in[6];
    const int* eidx = (const int*)d_in[7];
    const int* users = (const int*)d_in[8];
    const int* pos = (const int*)d_in[9];
    const int* neg = (const int*)d_in[10];
    float* out = (float*)d_out;

    const int* rows = eidx;
    const int* cols = eidx + NNZT;

    k_zero_cnt<<<(NTOT + 1 + 255) / 256, 256>>>();
    k_concat<<<(NTOT * (DEMB / 4) + 255) / 256, 256>>>((const float4*)ue, (const float4*)ie);
    k_count<<<(NNZT + 255) / 256, 256>>>(rows);
    k_scan1<<<SCAN_NBLK, 1024>>>();
    k_scan2<<<1, 32>>>();
    k_scan3<<<SCAN_NBLK, 1024>>>();
    k_fill<<<(NNZT + 255) / 256, 256>>>(rows, cols, ev);

    for (int l = 0; l < NLAYER; l++) {
        k_spmm<<<592, 512>>>(l);
        k_gemm<<<(NTOT + BM - 1) / BM, 128>>>(l, W1 + l * DEMB * DEMB, W2 + l * DEMB * DEMB,
                                              b1 + l * DEMB, b2 + l * DEMB);
    }
    k_gather<<<3 * BSZ, 256>>>(users, pos, neg, out);
}